// round 16
// baseline (speedup 1.0000x reference)
#include <cuda_runtime.h>
#include <math.h>

constexpr int H_ = 1024, G_ = 4096, B_ = 32, T_ = 64, S_ = 64, L_ = 2;
constexpr int KP  = 256;            // k per pass (step kernel)
constexpr int XST = 268;            // smem row stride (floats)
constexpr int BUF = 8608;           // floats per buffer region
constexpr int REDF = 8192;          // reduction scratch floats (32KB)
constexpr int SMEM_BYTES = (4 * BUF + REDF) * 4;   // 170496 B
constexpr int NBLK = 128;
constexpr int NGRP = 8;
constexpr int NT_ = 512;

// pre0 (occ-2) tiling
constexpr int KPL  = 128;           // k per pass
constexpr int XSTP = 132;           // row stride (floats)
constexpr int BUFP = 32 * XSTP + 32;        // 4256 floats
constexpr int REDP = 4096;
constexpr int SMEM_PRE0 = (4 * BUFP + REDP) * 4;   // 84480 B

// Scratch (device globals)
__device__ float g_pre0[(size_t)T_ * G_ * B_];   // [t][j][b]
__device__ float g_cw[(size_t)H_ * B_ * S_];     // CW[j][b][s]
__device__ float g_hbuf[2][L_][B_][H_];
__device__ float g_c[L_][B_][H_];
__device__ float g_gamma[2][B_][H_];             // parity double-buffered
__device__ float g_oh1[2][B_][H_];               // parity double-buffered
__device__ float g_scores[B_][S_];
__device__ unsigned g_cnt_sub[NGRP * 32];
__device__ unsigned g_cnt_top;
__device__ volatile unsigned g_gen;

__device__ __forceinline__ float sigf(float x) { return 1.f / (1.f + expf(-x)); }
__device__ __forceinline__ unsigned su32(const void* p) {
    return (unsigned)__cvta_generic_to_shared(p);
}
__device__ __forceinline__ float unpack_sum(unsigned long long u) {
    float lo, hi;
    asm("mov.b64 {%0,%1}, %2;" : "=f"(lo), "=f"(hi) : "l"(u));
    return lo + hi;
}
#define FMA2(a, x, w) asm("fma.rn.f32x2 %0, %1, %2, %0;" : "+l"(a) : "l"(x), "l"(w))

__device__ __forceinline__ void mb_init(unsigned long long* m) {
    asm volatile("mbarrier.init.shared.b64 [%0], 1;" :: "r"(su32(m)) : "memory");
}
__device__ __forceinline__ void mb_expect(unsigned mb, unsigned bytes) {
    asm volatile("mbarrier.arrive.expect_tx.shared.b64 _, [%0], %1;"
                 :: "r"(mb), "r"(bytes) : "memory");
}
__device__ __forceinline__ void mb_wait(unsigned mb, unsigned par) {
    asm volatile(
        "{\n\t.reg .pred P;\n\tW1_%=:\n\t"
        "mbarrier.try_wait.parity.acquire.cta.shared::cta.b64 P, [%0], %1, 0x989680;\n\t"
        "@P bra.uni W2_%=;\n\tbra.uni W1_%=;\n\tW2_%=:\n\t}"
        :: "r"(mb), "r"(par) : "memory");
}
__device__ __forceinline__ void bulkN(unsigned dst, const float* src, unsigned bytes,
                                      unsigned mb) {
    asm volatile(
        "cp.async.bulk.shared::cta.global.mbarrier::complete_tx::bytes [%0], [%1], %2, [%3];"
        :: "r"(dst), "l"(src), "r"(bytes), "r"(mb) : "memory");
}
__device__ __forceinline__ void bulk1k(unsigned dst, const float* src, unsigned mb) {
    bulkN(dst, src, 1024u, mb);
}

// Hierarchical grid barrier
__device__ __forceinline__ void grid_bar() {
    __syncthreads();
    if (threadIdx.x == 0) {
        __threadfence();
        unsigned gen = g_gen;
        if (atomicInc(&g_cnt_sub[(blockIdx.x & (NGRP - 1)) * 32],
                      NBLK / NGRP - 1) == NBLK / NGRP - 1) {
            if (atomicInc(&g_cnt_top, NGRP - 1) == NGRP - 1) g_gen = gen + 1;
        }
        while (g_gen == gen) __nanosleep(32);
        __threadfence();
    }
    __syncthreads();
}

__device__ __forceinline__ int skw(int r) { return ((r >> 3) & 7) * 4; }

// ---------------------------------------------------------------------------
// Job & staging (step kernel, 512 threads, KP=256).
// Weight smem row r: if (W2 && r>=8) -> W2 + (j0+(r&7))*ldw2
// else W(a/b by pass half) + (j0+(r&7)+(r>>3)*GS)*ldw.
// ---------------------------------------------------------------------------
struct Job {
    const float *Xa, *Xb;
    const int* toks;
    const float *Wa, *Wb, *W2;
    size_t ldw, ldw2;
    int j0, GS, nw;
};
struct Bufs {
    float *xb0, *xb1, *wb0, *wb1;
    unsigned mb0, mb1;
};

__device__ __forceinline__ void stage_w(const Bufs& Bf, const Job& J, int q, int tid) {
    const int s = q & 1;
    const unsigned mb = s ? Bf.mb1 : Bf.mb0;
    float* wb = s ? Bf.wb1 : Bf.wb0;
    if (tid == 0) mb_expect(mb, (unsigned)(32 + J.nw) * 1024u);
    __syncthreads();   // all warps done reading this buffer pair
    if (tid >= 32 && tid < 32 + J.nw) {
        int r = tid - 32;
        const float* src;
        const int k0 = (q & 3) * KP;
        if (J.W2 && r >= 8)
            src = J.W2 + (size_t)(J.j0 + (r & 7)) * J.ldw2 + k0;
        else {
            const float* W = (q >= 4) ? J.Wb : J.Wa;
            src = W + (size_t)(J.j0 + (r & 7) + (r >> 3) * J.GS) * J.ldw + k0;
        }
        bulk1k(su32(wb + r * XST + skw(r)), src, mb);
    }
}
__device__ __forceinline__ void stage_x(const Bufs& Bf, const Job& J, int q, int tid) {
    const int s = q & 1;
    const unsigned mb = s ? Bf.mb1 : Bf.mb0;
    float* xb = s ? Bf.xb1 : Bf.xb0;
    if (tid < 32) {
        const float* X = (q >= 4) ? J.Xb : J.Xa;
        const int k0 = (q & 3) * KP;
        const float* src = J.toks ? J.Xa + (size_t)J.toks[tid] * H_ + k0
                                  : X + (size_t)tid * H_ + k0;
        bulk1k(su32(xb + tid * XST + skw(tid)), src, mb);
    }
}

// 32-row compute: warp = (ks=wid&7 k-slice of 32, rh=wid>>3 row half), 8r x 2b
__device__ __forceinline__ void comp32(const float* xb, const float* wb,
                                       unsigned long long* acc, int wid, int lane) {
    const int ks = wid & 7, rh = wid >> 3;
    const int bp = lane & 15, rg = lane >> 4;
    const int R0 = rh * 16 + rg * 8;
    const float* xp0 = xb + (2 * bp) * XST + skw(2 * bp) + ks * 32;
    const float* wp  = wb + R0 * XST + skw(R0) + ks * 32;
#pragma unroll
    for (int kq = 0; kq < 32; kq += 4) {
        ulonglong2 x0 = *(const ulonglong2*)(xp0 + kq);
        ulonglong2 x1 = *(const ulonglong2*)(xp0 + XST + kq);
#pragma unroll
        for (int r = 0; r < 8; r++) {
            ulonglong2 wv = *(const ulonglong2*)(wp + r * XST + kq);
            FMA2(acc[2 * r],     x0.x, wv.x); FMA2(acc[2 * r],     x0.y, wv.y);
            FMA2(acc[2 * r + 1], x1.x, wv.x); FMA2(acc[2 * r + 1], x1.y, wv.y);
        }
    }
}
// fused 16-row (gamma rows 0-7, oh1 rows 8-15): oct=wid>>3, ks=wid&7
__device__ __forceinline__ void compFU(const float* xb, const float* wb,
                                       unsigned long long* acc, int wid, int lane) {
    const int ks = wid & 7, oct = wid >> 3;
    const int bp = lane & 15, kk = lane >> 4;
    const int ko = ks * 32 + kk * 16;
    const float* xp0 = xb + (2 * bp) * XST + skw(2 * bp) + ko;
    const float* wp  = wb + (oct * 8) * XST + skw(oct * 8) + ko;
#pragma unroll
    for (int kq = 0; kq < 16; kq += 4) {
        ulonglong2 x0 = *(const ulonglong2*)(xp0 + kq);
        ulonglong2 x1 = *(const ulonglong2*)(xp0 + XST + kq);
#pragma unroll
        for (int r = 0; r < 8; r++) {
            ulonglong2 wv = *(const ulonglong2*)(wp + r * XST + kq);
            FMA2(acc[2 * r],     x0.x, wv.x); FMA2(acc[2 * r],     x0.y, wv.y);
            FMA2(acc[2 * r + 1], x1.x, wv.x); FMA2(acc[2 * r + 1], x1.y, wv.y);
        }
    }
}

// Consumer loop; last two passes prestage nextJ's passes 0,1 (weights; x opt).
template <int NPK, int MODE>
__device__ void run_job(const Bufs& Bf, const Job& J, const Job* nextJ, bool nextX,
                        unsigned long long* acc, unsigned* ph,
                        int tid, int wid, int lane) {
#pragma unroll
    for (int p = 0; p < NPK; p++) {
        const int s = p & 1;
        mb_wait(s ? Bf.mb1 : Bf.mb0, ph[s] & 1);
        ph[s]++;
        const float* xb = s ? Bf.xb1 : Bf.xb0;
        const float* wb = s ? Bf.wb1 : Bf.wb0;
        if (MODE == 0) comp32(xb, wb, acc, wid, lane);
        else           compFU(xb, wb, acc, wid, lane);
        if (p + 2 < NPK) {
            stage_w(Bf, J, p + 2, tid);
            stage_x(Bf, J, p + 2, tid);
        } else if (nextJ) {
            int q = p + 2 - NPK;
            stage_w(Bf, *nextJ, q, tid);
            if (nextX) stage_x(Bf, *nextJ, q, tid);
        }
    }
}

// ---- single-round reductions (red = 32KB) ----
__device__ __forceinline__ void red32_write(float* red, const unsigned long long* acc,
                                            int wid, int lane) {
    const int ks = wid & 7, rh = wid >> 3, bp = lane & 15, rg = lane >> 4;
    const int R0 = rh * 16 + rg * 8;
#pragma unroll
    for (int r = 0; r < 8; r++) {
        float2 v = make_float2(unpack_sum(acc[2 * r]), unpack_sum(acc[2 * r + 1]));
        *(float2*)&red[ks * 1024 + (R0 + r) * 32 + 2 * bp] = v;
    }
}
__device__ __forceinline__ float red32_sum8(const float* red, int row, int b) {
    float s = 0.f;
#pragma unroll
    for (int i = 0; i < 8; i++) s += red[i * 1024 + row * 32 + b];
    return s;
}
__device__ __forceinline__ void fu_write(float* red, const unsigned long long* acc,
                                         int wid, int lane) {
    const int ks = wid & 7, oct = wid >> 3;
    const int bp = lane & 15, kk = lane >> 4;
    const int sl = ks * 2 + kk;
#pragma unroll
    for (int r = 0; r < 8; r++) {
        float2 v = make_float2(unpack_sum(acc[2 * r]), unpack_sum(acc[2 * r + 1]));
        *(float2*)&red[oct * 4096 + sl * 256 + r * 32 + 2 * bp] = v;
    }
}
__device__ __forceinline__ float fu_sum16(const float* red, int oct, int row, int b) {
    float s = 0.f;
#pragma unroll
    for (int i = 0; i < 16; i++) s += red[oct * 4096 + i * 256 + row * 32 + b];
    return s;
}

// out epilogue for step tt (oh1 parity = par); CW read from L2-resident g_cw.
__device__ __forceinline__ void out_epi(float* red, float b_out_r,
                                        float* __restrict__ out,
                                        int tt, int par, int j, int jl, int b,
                                        int tid, int wid, int lane) {
    __syncthreads();   // red free for reuse
    if (wid < 16) {
#pragma unroll
        for (int rep = 0; rep < 2; rep++) {
            int b2 = wid * 2 + rep;
            float v0 = g_scores[b2][lane], v1 = g_scores[b2][lane + 32];
            float m = fmaxf(v0, v1);
#pragma unroll
            for (int o = 16; o; o >>= 1) m = fmaxf(m, __shfl_xor_sync(0xffffffffu, m, o));
            float e0 = expf(v0 - m), e1 = expf(v1 - m);
            float ssum = e0 + e1;
#pragma unroll
            for (int o = 16; o; o >>= 1) ssum += __shfl_xor_sync(0xffffffffu, ssum, o);
            float inv = 1.f / ssum;
            red[b2 * 65 + lane] = e0 * inv;
            red[b2 * 65 + lane + 32] = e1 * inv;
        }
    }
    __syncthreads();
    if (tid < 256) {
        const float* cw = g_cw + (size_t)j * (B_ * S_) + b * S_;
        const float* wp = red + b * 65;
        float a = g_oh1[par][b][j] + b_out_r;
#pragma unroll
        for (int s4 = 0; s4 < 16; s4++) {
            float4 c = *(const float4*)(cw + s4 * 4);
            a += wp[s4 * 4 + 0] * c.x + wp[s4 * 4 + 1] * c.y +
                 wp[s4 * 4 + 2] * c.z + wp[s4 * 4 + 3] * c.w;
        }
        out[(size_t)tt * B_ * H_ + (size_t)b * H_ + j] = tanhf(a);
    }
    __syncthreads();
}

// scores for parity pg: all 128 blocks, 16 (b,s) dots each
__device__ __forceinline__ void scores_phase(float* red,
                                             const float* __restrict__ contexts,
                                             int pg, int blk, int tid, int wid, int lane) {
    __syncthreads();
    const int bb = blk & 31, sg = blk >> 5;
    const float* gam = &g_gamma[pg][bb][0];
    for (int i = tid; i < H_; i += NT_) red[i] = gam[i];
    __syncthreads();
    if (wid < 16) {
        int s = sg * 16 + wid;
        const float* cp = contexts + ((size_t)bb * S_ + s) * H_;
        float a = 0.f;
#pragma unroll 8
        for (int k = lane; k < H_; k += 32) a = fmaf(cp[k], red[k], a);
#pragma unroll
        for (int o = 16; o; o >>= 1) a += __shfl_xor_sync(0xffffffffu, a, o);
        if (lane == 0) g_scores[bb][s] = a;
    }
    __syncthreads();
}

// ===========================================================================
// Persistent step kernel. grid NBLK x 512. Software-pipelined, 2 bars/step:
//   prologue A(0) |B|
//   for t: alpha(t): B(t) -> A(t+1) -> out_epi(t-2)   |B|
//          beta(t):  FU(t) -> scores(t-1)             |B|
//   tail: out_epi(T-2) |B| scores(T-1) |B| out_epi(T-1)
// ===========================================================================
__global__ void __launch_bounds__(NT_, 1) k_steps(const float* __restrict__ Whh0,
                                                  const float* __restrict__ Wih1,
                                                  const float* __restrict__ Whh1,
                                                  const float* __restrict__ bih1,
                                                  const float* __restrict__ bhh1,
                                                  const float* __restrict__ W_in,
                                                  const float* __restrict__ b_in,
                                                  const float* __restrict__ W_out,
                                                  const float* __restrict__ b_out,
                                                  const float* __restrict__ contexts,
                                                  float* __restrict__ out) {
    extern __shared__ float sm[];
    __shared__ unsigned long long mbar[2];
    const int tid = threadIdx.x, wid = tid >> 5, lane = tid & 31;
    const int blk = blockIdx.x;
    const int jl = tid >> 5, b = tid & 31;   // epilogue map (tid<256)
    const int j = blk * 8 + jl;
    float* red = sm + 4 * BUF;

    if (tid == 0) { mb_init(&mbar[0]); mb_init(&mbar[1]); }
    __syncthreads();
    Bufs Bf = {sm, sm + 2 * BUF, sm + BUF, sm + 3 * BUF,
               su32(&mbar[0]), su32(&mbar[1])};
    unsigned ph[2] = {0u, 0u};

    // hoisted per-thread constants
    float bi1[4], b_in_r = 0.f, b_out_r = 0.f;
    if (tid < 256) {
#pragma unroll
        for (int g = 0; g < 4; g++) bi1[g] = bih1[g * H_ + j] + bhh1[g * H_ + j];
        b_in_r = b_in[j];
        b_out_r = b_out[j];
    }

    // ---- prologue: A(0) = cell0(t=0) ----
    {
        Job A0 = {&g_hbuf[1][0][0][0], nullptr, nullptr, Whh0, nullptr, nullptr,
                  (size_t)H_, 0, blk * 8, H_, 32};
        Job B0 = {&g_hbuf[0][0][0][0], &g_hbuf[1][1][0][0], nullptr,
                  Wih1, Whh1, nullptr, (size_t)H_, 0, blk * 8, H_, 32};
        stage_w(Bf, A0, 0, tid); stage_x(Bf, A0, 0, tid);
        stage_w(Bf, A0, 1, tid); stage_x(Bf, A0, 1, tid);
        unsigned long long acc[16] = {};
        run_job<4, 0>(Bf, A0, &B0, false, acc, ph, tid, wid, lane);
        __syncthreads();
        red32_write(red, acc, wid, lane);
        __syncthreads();
        if (tid < 256) {
            float v[4];
#pragma unroll
            for (int g = 0; g < 4; g++)
                v[g] = red32_sum8(red, g * 8 + jl, b) +
                       g_pre0[(size_t)(g * H_ + j) * B_ + b];
            float c1 = sigf(v[1]) * g_c[0][b][j] + sigf(v[0]) * tanhf(v[2]);
            g_c[0][b][j] = c1;
            g_hbuf[0][0][b][j] = sigf(v[3]) * tanhf(c1);
        }
    }
    grid_bar();

    for (int t = 0; t < T_; t++) {
        const int cur = t & 1;
        const bool hasA = (t + 1 < T_);

        Job Bt = {&g_hbuf[cur][0][0][0], &g_hbuf[1 - cur][1][0][0], nullptr,
                  Wih1, Whh1, nullptr, (size_t)H_, 0, blk * 8, H_, 32};
        Job An = {&g_hbuf[cur][0][0][0], nullptr, nullptr, Whh0, nullptr, nullptr,
                  (size_t)H_, 0, blk * 8, H_, 32};
        Job FUt = {&g_hbuf[cur][1][0][0], nullptr, nullptr,
                   W_in, nullptr, W_out + H_, (size_t)H_, (size_t)(2 * H_),
                   blk * 8, 8, 16};
        Job Bn = {&g_hbuf[1 - cur][0][0][0], &g_hbuf[cur][1][0][0], nullptr,
                  Wih1, Whh1, nullptr, (size_t)H_, 0, blk * 8, H_, 32};

        // ============ alpha(t): cell1(t), cell0(t+1), out_epi(t-2) ============
        if (t == 0) {   // t>0: beta(t-1) already prestaged Bt fully (w + x)
            stage_x(Bf, Bt, 0, tid);
            stage_x(Bf, Bt, 1, tid);
        }

        // prefetch pre0[t+1]
        float p[4];
        if (hasA && tid < 256) {
            const float* pre = g_pre0 + (size_t)(t + 1) * G_ * B_;
#pragma unroll
            for (int g = 0; g < 4; g++) p[g] = pre[(size_t)(g * H_ + j) * B_ + b];
        }

        {   // B(t) = cell1(t)
            unsigned long long acc[16] = {};
            if (hasA) run_job<8, 0>(Bf, Bt, &An, true, acc, ph, tid, wid, lane);
            else      run_job<8, 0>(Bf, Bt, &FUt, false, acc, ph, tid, wid, lane);
            __syncthreads();
            red32_write(red, acc, wid, lane);
            __syncthreads();
            if (tid < 256) {
                float v[4];
#pragma unroll
                for (int g = 0; g < 4; g++)
                    v[g] = red32_sum8(red, g * 8 + jl, b) + bi1[g];
                float c1 = sigf(v[1]) * g_c[1][b][j] + sigf(v[0]) * tanhf(v[2]);
                g_c[1][b][j] = c1;
                g_hbuf[cur][1][b][j] = sigf(v[3]) * tanhf(c1);
            }
        }
        if (hasA) {  // A(t+1) = cell0(t+1)
            unsigned long long acc[16] = {};
            run_job<4, 0>(Bf, An, &FUt, false, acc, ph, tid, wid, lane);
            __syncthreads();
            red32_write(red, acc, wid, lane);
            __syncthreads();
            if (tid < 256) {
                float v[4];
#pragma unroll
                for (int g = 0; g < 4; g++)
                    v[g] = red32_sum8(red, g * 8 + jl, b) + p[g];
                float c1 = sigf(v[1]) * g_c[0][b][j] + sigf(v[0]) * tanhf(v[2]);
                g_c[0][b][j] = c1;
                g_hbuf[1 - cur][0][b][j] = sigf(v[3]) * tanhf(c1);
            }
        }
        if (t >= 2) out_epi(red, b_out_r, out, t - 2, cur, j, jl, b, tid, wid, lane);
        grid_bar();

        // ============ beta(t): FU(t) = gamma+oh1, scores(t-1) ============
        stage_x(Bf, FUt, 0, tid);
        stage_x(Bf, FUt, 1, tid);
        {
            unsigned long long acc[16] = {};
            // prestage NEXT step's cell1 fully: its x (h0(t+1), h1(t)) are
            // published and barrier-ordered at this point.
            if (hasA) run_job<4, 1>(Bf, FUt, &Bn, true, acc, ph, tid, wid, lane);
            else      run_job<4, 1>(Bf, FUt, nullptr, false, acc, ph, tid, wid, lane);
            __syncthreads();
            fu_write(red, acc, wid, lane);
            __syncthreads();
            if (tid < 256) {
                g_gamma[cur][b][j] = fu_sum16(red, 0, jl, b) + b_in_r;
                g_oh1[cur][b][j]   = fu_sum16(red, 1, jl, b);
            }
        }
        if (t >= 1) scores_phase(red, contexts, 1 - cur, blk, tid, wid, lane);
        grid_bar();
    }

    // ---- tail ----
    out_epi(red, b_out_r, out, T_ - 2, (T_ - 2) & 1, j, jl, b, tid, wid, lane);
    grid_bar();
    scores_phase(red, contexts, (T_ - 1) & 1, blk, tid, wid, lane);
    grid_bar();
    out_epi(red, b_out_r, out, T_ - 1, (T_ - 1) & 1, j, jl, b, tid, wid, lane);
}

// ===========================================================================
// pre0 (occ-2): grid (G/32, T) x 256 threads, KPL=128, 8 passes.
// 8 warps: ks = wid&3 (k-slice of 32), rh = wid>>2 (row half); 8r x 2b tile.
// ===========================================================================
__device__ __forceinline__ void stage_p(float* xb, float* wb, unsigned mb,
                                        const float* __restrict__ emb, const int* toks,
                                        const float* __restrict__ W, int j0,
                                        int q, int tid) {
    if (tid == 0) mb_expect(mb, 64u * (KPL * 4));
    __syncthreads();
    const int k0 = (q & 7) * KPL;
    if (tid < 32) {
        bulkN(su32(xb + tid * XSTP + skw(tid)),
              emb + (size_t)toks[tid] * H_ + k0, KPL * 4, mb);
    } else if (tid < 64) {
        int r = tid - 32;
        bulkN(su32(wb + r * XSTP + skw(r)),
              W + (size_t)(j0 + r) * H_ + k0, KPL * 4, mb);
    }
}
__device__ __forceinline__ void comp_p(const float* xb, const float* wb,
                                       unsigned long long* acc, int wid, int lane) {
    const int ks = wid & 3, rh = wid >> 2;
    const int bp = lane & 15, rg = lane >> 4;
    const int R0 = rh * 16 + rg * 8;
    const float* xp0 = xb + (2 * bp) * XSTP + skw(2 * bp) + ks * 32;
    const float* wp  = wb + R0 * XSTP + skw(R0) + ks * 32;
#pragma unroll
    for (int kq = 0; kq < 32; kq += 4) {
        ulonglong2 x0 = *(const ulonglong2*)(xp0 + kq);
        ulonglong2 x1 = *(const ulonglong2*)(xp0 + XSTP + kq);
#pragma unroll
        for (int r = 0; r < 8; r++) {
            ulonglong2 wv = *(const ulonglong2*)(wp + r * XSTP + kq);
            FMA2(acc[2 * r],     x0.x, wv.x); FMA2(acc[2 * r],     x0.y, wv.y);
            FMA2(acc[2 * r + 1], x1.x, wv.x); FMA2(acc[2 * r + 1], x1.y, wv.y);
        }
    }
}

__global__ void __launch_bounds__(256, 2) k_pre0(const int* __restrict__ tokens,
                                                 const float* __restrict__ emb,
                                                 const float* __restrict__ Wih0,
                                                 const float* __restrict__ bih0,
                                                 const float* __restrict__ bhh0) {
    extern __shared__ float sm[];
    __shared__ unsigned long long mbar[2];
    __shared__ int toks[B_];
    const int tid = threadIdx.x, wid = tid >> 5, lane = tid & 31;
    const int t = blockIdx.y;
    const int j0 = blockIdx.x * 32;
    float* xb[2] = {sm, sm + 2 * BUFP};
    float* wb[2] = {sm + BUFP, sm + 3 * BUFP};
    float* red = sm + 4 * BUFP;

    if (tid == 0) { mb_init(&mbar[0]); mb_init(&mbar[1]); }
    if (tid < B_) toks[tid] = tokens[t * B_ + tid];
    __syncthreads();
    unsigned mbs[2] = {su32(&mbar[0]), su32(&mbar[1])};
    unsigned ph[2] = {0u, 0u};

    stage_p(xb[0], wb[0], mbs[0], emb, toks, Wih0, j0, 0, tid);
    stage_p(xb[1], wb[1], mbs[1], emb, toks, Wih0, j0, 1, tid);

    unsigned long long acc[16] = {};
    for (int p = 0; p < 8; p++) {
        const int s = p & 1;
        mb_wait(mbs[s], ph[s] & 1);
        ph[s]++;
        comp_p(xb[s], wb[s], acc, wid, lane);
        if (p + 2 < 8)
            stage_p(xb[s], wb[s], mbs[s], emb, toks, Wih0, j0, p + 2, tid);
    }
    __syncthreads();
    {   // single-round reduction: slot ks in [0,4)
        const int ks = wid & 3, rh = wid >> 2, bp = lane & 15, rg = lane >> 4;
        const int R0 = rh * 16 + rg * 8;
#pragma unroll
        for (int r = 0; r < 8; r++) {
            float2 v = make_float2(unpack_sum(acc[2 * r]), unpack_sum(acc[2 * r + 1]));
            *(float2*)&red[ks * 1024 + (R0 + r) * 32 + 2 * bp] = v;
        }
    }
    __syncthreads();
    const int rl = tid >> 5, b = tid & 31;
#pragma unroll
    for (int i = 0; i < 4; i++) {
        int row = rl + i * 8;
        int jj = j0 + row;
        float s = red[row * 32 + b] + red[1024 + row * 32 + b] +
                  red[2048 + row * 32 + b] + red[3072 + row * 32 + b];
        g_pre0[((size_t)t * G_ + jj) * B_ + b] = s + bih0[jj] + bhh0[jj];
    }
}

// ===========================================================================
// CW precompute: CW[j][b][s] = contexts[b,s,:].W_out[j,:H]
// grid (H/32 j-tiles, B*S/32 bs-tiles) x 512, single-round red.
// ===========================================================================
__global__ void __launch_bounds__(NT_, 1) k_cw(const float* __restrict__ contexts,
                                               const float* __restrict__ W_out) {
    extern __shared__ float sm[];
    __shared__ unsigned long long mbar[2];
    const int tid = threadIdx.x, wid = tid >> 5, lane = tid & 31;
    const int j0 = blockIdx.x * 32;
    const int bs0 = blockIdx.y * 32;
    float* red = sm + 4 * BUF;

    if (tid == 0) { mb_init(&mbar[0]); mb_init(&mbar[1]); }
    __syncthreads();
    Bufs Bf = {sm, sm + 2 * BUF, sm + BUF, sm + 3 * BUF,
               su32(&mbar[0]), su32(&mbar[1])};
    unsigned ph[2] = {0u, 0u};

    Job P = {contexts + (size_t)bs0 * H_, nullptr, nullptr,
             W_out, nullptr, nullptr, (size_t)(2 * H_), 0, j0, 8, 32};
    stage_w(Bf, P, 0, tid); stage_x(Bf, P, 0, tid);
    stage_w(Bf, P, 1, tid); stage_x(Bf, P, 1, tid);

    unsigned long long acc[16] = {};
    run_job<4, 0>(Bf, P, nullptr, false, acc, ph, tid, wid, lane);
    __syncthreads();
    red32_write(red, acc, wid, lane);
    __syncthreads();

    const int rl = tid >> 5, b = tid & 31;
#pragma unroll
    for (int i = 0; i < 2; i++) {
        int row = rl + i * 16;
        g_cw[(size_t)(j0 + row) * (B_ * S_) + bs0 + b] = red32_sum8(red, row, b);
    }
}

// ---------------------------------------------------------------------------
extern "C" void kernel_launch(void* const* d_in, const int* in_sizes, int n_in,
                              void* d_out, int out_size) {
    const int*   tokens   = (const int*)d_in[0];
    const float* h0       = (const float*)d_in[1];
    const float* c0       = (const float*)d_in[2];
    const float* contexts = (const float*)d_in[3];
    const float* emb      = (const float*)d_in[4];
    const float* W_ih     = (const float*)d_in[5];
    const float* W_hh     = (const float*)d_in[6];
    const float* b_ih     = (const float*)d_in[7];
    const float* b_hh     = (const float*)d_in[8];
    const float* W_in     = (const float*)d_in[9];
    const float* b_in     = (const float*)d_in[10];
    const float* W_out    = (const float*)d_in[11];
    const float* b_out    = (const float*)d_in[12];
    float* out = (float*)d_out;

    cudaFuncSetAttribute(k_pre0,  cudaFuncAttributeMaxDynamicSharedMemorySize, SMEM_PRE0);
    cudaFuncSetAttribute(k_cw,    cudaFuncAttributeMaxDynamicSharedMemorySize, SMEM_BYTES);
    cudaFuncSetAttribute(k_steps, cudaFuncAttributeMaxDynamicSharedMemorySize, SMEM_BYTES);

    const size_t stateBytes = (size_t)L_ * B_ * H_ * sizeof(float);

    // init state: h -> hbuf[1] (prev of t=0), c -> g_c
    cudaMemcpyToSymbolAsync(g_hbuf, h0, stateBytes, stateBytes,
                            cudaMemcpyDeviceToDevice, 0);
    cudaMemcpyToSymbolAsync(g_c, c0, stateBytes, 0, cudaMemcpyDeviceToDevice, 0);

    // hoisted precomputes
    k_pre0<<<dim3(G_ / 32, T_), 256, SMEM_PRE0>>>(tokens, emb, W_ih, b_ih, b_hh);
    k_cw<<<dim3(H_ / 32, (B_ * S_) / 32), NT_, SMEM_BYTES>>>(contexts, W_out);

    const float* Wih1 = W_ih + (size_t)G_ * H_;
    const float* Whh1 = W_hh + (size_t)G_ * H_;
    const float* bih1 = b_ih + G_;
    const float* bhh1 = b_hh + G_;

    // entire recurrence in ONE persistent kernel
    k_steps<<<NBLK, NT_, SMEM_BYTES>>>(W_hh, Wih1, Whh1, bih1, bhh1,
                                       W_in, b_in, W_out, b_out, contexts, out);

    // hT (in hbuf[1] since (T-1)&1 == 1), then cT
    cudaMemcpyFromSymbolAsync(out + (size_t)T_ * B_ * H_, g_hbuf, stateBytes,
                              stateBytes, cudaMemcpyDeviceToDevice, 0);
    cudaMemcpyFromSymbolAsync(out + (size_t)T_ * B_ * H_ + (size_t)L_ * B_ * H_,
                              g_c, stateBytes, 0, cudaMemcpyDeviceToDevice, 0);
}

// round 17
// speedup vs baseline: 1.0300x; 1.0300x over previous
#include <cuda_runtime.h>
#include <math.h>

constexpr int H_ = 1024, G_ = 4096, B_ = 32, T_ = 64, S_ = 64, L_ = 2;
constexpr int KP  = 256;            // k per pass
constexpr int XST = 268;            // smem row stride (floats)
constexpr int BUF = 8608;           // floats per buffer region
constexpr int REDF = 8192;          // reduction scratch floats (32KB)
constexpr int SMEM_BYTES = (4 * BUF + REDF) * 4;   // 170496 B
constexpr int NBLK = 128;
constexpr int NGRP = 8;
constexpr int NT_ = 512;

// Scratch (device globals)
__device__ float g_pre0[(size_t)T_ * G_ * B_];   // [t][j][b]
__device__ float g_cw[(size_t)H_ * B_ * S_];     // CW[j][b][s]
__device__ float g_hbuf[2][L_][B_][H_];
__device__ float g_c[L_][B_][H_];
__device__ float g_gamma[2][B_][H_];             // parity double-buffered
__device__ float g_oh1[2][B_][H_];               // parity double-buffered
__device__ float g_scores[B_][S_];
__device__ unsigned g_cnt_sub[NGRP * 32];
__device__ unsigned g_cnt_top;
__device__ volatile unsigned g_gen;

__device__ __forceinline__ float sigf(float x) { return 1.f / (1.f + expf(-x)); }
__device__ __forceinline__ unsigned su32(const void* p) {
    return (unsigned)__cvta_generic_to_shared(p);
}
__device__ __forceinline__ float unpack_sum(unsigned long long u) {
    float lo, hi;
    asm("mov.b64 {%0,%1}, %2;" : "=f"(lo), "=f"(hi) : "l"(u));
    return lo + hi;
}
#define FMA2(a, x, w) asm("fma.rn.f32x2 %0, %1, %2, %0;" : "+l"(a) : "l"(x), "l"(w))

__device__ __forceinline__ void mb_init(unsigned long long* m) {
    asm volatile("mbarrier.init.shared.b64 [%0], 1;" :: "r"(su32(m)) : "memory");
}
__device__ __forceinline__ void mb_expect(unsigned mb, unsigned bytes) {
    asm volatile("mbarrier.arrive.expect_tx.shared.b64 _, [%0], %1;"
                 :: "r"(mb), "r"(bytes) : "memory");
}
__device__ __forceinline__ void mb_wait(unsigned mb, unsigned par) {
    asm volatile(
        "{\n\t.reg .pred P;\n\tW1_%=:\n\t"
        "mbarrier.try_wait.parity.acquire.cta.shared::cta.b64 P, [%0], %1, 0x989680;\n\t"
        "@P bra.uni W2_%=;\n\tbra.uni W1_%=;\n\tW2_%=:\n\t}"
        :: "r"(mb), "r"(par) : "memory");
}
__device__ __forceinline__ void bulk1k(unsigned dst, const float* src, unsigned mb) {
    asm volatile(
        "cp.async.bulk.shared::cta.global.mbarrier::complete_tx::bytes [%0], [%1], 1024, [%2];"
        :: "r"(dst), "l"(src), "r"(mb) : "memory");
}

// Hierarchical grid barrier
__device__ __forceinline__ void grid_bar() {
    __syncthreads();
    if (threadIdx.x == 0) {
        __threadfence();
        unsigned gen = g_gen;
        if (atomicInc(&g_cnt_sub[(blockIdx.x & (NGRP - 1)) * 32],
                      NBLK / NGRP - 1) == NBLK / NGRP - 1) {
            if (atomicInc(&g_cnt_top, NGRP - 1) == NGRP - 1) g_gen = gen + 1;
        }
        while (g_gen == gen) __nanosleep(32);
        __threadfence();
    }
    __syncthreads();
}

__device__ __forceinline__ int skw(int r) { return ((r >> 3) & 7) * 4; }

// ---------------------------------------------------------------------------
// Job & staging. Weight smem row r: if (W2 && r>=8) -> W2 + (j0+(r&7))*ldw2
// else W(a/b by pass half) + (j0+(r&7)+(r>>3)*GS)*ldw.
// ---------------------------------------------------------------------------
struct Job {
    const float *Xa, *Xb;
    const int* toks;
    const float *Wa, *Wb, *W2;
    size_t ldw, ldw2;
    int j0, GS, nw;
};
struct Bufs {
    float *xb0, *xb1, *wb0, *wb1;
    unsigned mb0, mb1;
};

__device__ __forceinline__ void stage_w(const Bufs& Bf, const Job& J, int q, int tid) {
    const int s = q & 1;
    const unsigned mb = s ? Bf.mb1 : Bf.mb0;
    float* wb = s ? Bf.wb1 : Bf.wb0;
    if (tid == 0) mb_expect(mb, (unsigned)(32 + J.nw) * 1024u);
    __syncthreads();   // all warps done reading this buffer pair
    if (tid >= 32 && tid < 32 + J.nw) {
        int r = tid - 32;
        const float* src;
        const int k0 = (q & 3) * KP;
        if (J.W2 && r >= 8)
            src = J.W2 + (size_t)(J.j0 + (r & 7)) * J.ldw2 + k0;
        else {
            const float* W = (q >= 4) ? J.Wb : J.Wa;
            src = W + (size_t)(J.j0 + (r & 7) + (r >> 3) * J.GS) * J.ldw + k0;
        }
        bulk1k(su32(wb + r * XST + skw(r)), src, mb);
    }
}
__device__ __forceinline__ void stage_x(const Bufs& Bf, const Job& J, int q, int tid) {
    const int s = q & 1;
    const unsigned mb = s ? Bf.mb1 : Bf.mb0;
    float* xb = s ? Bf.xb1 : Bf.xb0;
    if (tid < 32) {
        const float* X = (q >= 4) ? J.Xb : J.Xa;
        const int k0 = (q & 3) * KP;
        const float* src = J.toks ? J.Xa + (size_t)J.toks[tid] * H_ + k0
                                  : X + (size_t)tid * H_ + k0;
        bulk1k(su32(xb + tid * XST + skw(tid)), src, mb);
    }
}

// 32-row compute: warp = (ks=wid&7 k-slice of 32, rh=wid>>3 row half), 8r x 2b
__device__ __forceinline__ void comp32(const float* xb, const float* wb,
                                       unsigned long long* acc, int wid, int lane) {
    const int ks = wid & 7, rh = wid >> 3;
    const int bp = lane & 15, rg = lane >> 4;
    const int R0 = rh * 16 + rg * 8;
    const float* xp0 = xb + (2 * bp) * XST + skw(2 * bp) + ks * 32;
    const float* wp  = wb + R0 * XST + skw(R0) + ks * 32;
#pragma unroll
    for (int kq = 0; kq < 32; kq += 4) {
        ulonglong2 x0 = *(const ulonglong2*)(xp0 + kq);
        ulonglong2 x1 = *(const ulonglong2*)(xp0 + XST + kq);
#pragma unroll
        for (int r = 0; r < 8; r++) {
            ulonglong2 wv = *(const ulonglong2*)(wp + r * XST + kq);
            FMA2(acc[2 * r],     x0.x, wv.x); FMA2(acc[2 * r],     x0.y, wv.y);
            FMA2(acc[2 * r + 1], x1.x, wv.x); FMA2(acc[2 * r + 1], x1.y, wv.y);
        }
    }
}
// fused 16-row (gamma rows 0-7, oh1 rows 8-15): oct=wid>>3, ks=wid&7
__device__ __forceinline__ void compFU(const float* xb, const float* wb,
                                       unsigned long long* acc, int wid, int lane) {
    const int ks = wid & 7, oct = wid >> 3;
    const int bp = lane & 15, kk = lane >> 4;
    const int ko = ks * 32 + kk * 16;
    const float* xp0 = xb + (2 * bp) * XST + skw(2 * bp) + ko;
    const float* wp  = wb + (oct * 8) * XST + skw(oct * 8) + ko;
#pragma unroll
    for (int kq = 0; kq < 16; kq += 4) {
        ulonglong2 x0 = *(const ulonglong2*)(xp0 + kq);
        ulonglong2 x1 = *(const ulonglong2*)(xp0 + XST + kq);
#pragma unroll
        for (int r = 0; r < 8; r++) {
            ulonglong2 wv = *(const ulonglong2*)(wp + r * XST + kq);
            FMA2(acc[2 * r],     x0.x, wv.x); FMA2(acc[2 * r],     x0.y, wv.y);
            FMA2(acc[2 * r + 1], x1.x, wv.x); FMA2(acc[2 * r + 1], x1.y, wv.y);
        }
    }
}

// Consumer loop; last two passes prestage nextJ's passes 0,1 (weights; x opt).
template <int NPK, int MODE>
__device__ void run_job(const Bufs& Bf, const Job& J, const Job* nextJ, bool nextX,
                        unsigned long long* acc, unsigned* ph,
                        int tid, int wid, int lane) {
#pragma unroll
    for (int p = 0; p < NPK; p++) {
        const int s = p & 1;
        mb_wait(s ? Bf.mb1 : Bf.mb0, ph[s] & 1);
        ph[s]++;
        const float* xb = s ? Bf.xb1 : Bf.xb0;
        const float* wb = s ? Bf.wb1 : Bf.wb0;
        if (MODE == 0) comp32(xb, wb, acc, wid, lane);
        else           compFU(xb, wb, acc, wid, lane);
        if (p + 2 < NPK) {
            stage_w(Bf, J, p + 2, tid);
            stage_x(Bf, J, p + 2, tid);
        } else if (nextJ) {
            int q = p + 2 - NPK;
            stage_w(Bf, *nextJ, q, tid);
            if (nextX) stage_x(Bf, *nextJ, q, tid);
        }
    }
}

// ---- single-round reductions (red = 32KB) ----
__device__ __forceinline__ void red32_write(float* red, const unsigned long long* acc,
                                            int wid, int lane) {
    const int ks = wid & 7, rh = wid >> 3, bp = lane & 15, rg = lane >> 4;
    const int R0 = rh * 16 + rg * 8;
#pragma unroll
    for (int r = 0; r < 8; r++) {
        float2 v = make_float2(unpack_sum(acc[2 * r]), unpack_sum(acc[2 * r + 1]));
        *(float2*)&red[ks * 1024 + (R0 + r) * 32 + 2 * bp] = v;
    }
}
__device__ __forceinline__ float red32_sum8(const float* red, int row, int b) {
    float s = 0.f;
#pragma unroll
    for (int i = 0; i < 8; i++) s += red[i * 1024 + row * 32 + b];
    return s;
}
__device__ __forceinline__ void fu_write(float* red, const unsigned long long* acc,
                                         int wid, int lane) {
    const int ks = wid & 7, oct = wid >> 3;
    const int bp = lane & 15, kk = lane >> 4;
    const int sl = ks * 2 + kk;
#pragma unroll
    for (int r = 0; r < 8; r++) {
        float2 v = make_float2(unpack_sum(acc[2 * r]), unpack_sum(acc[2 * r + 1]));
        *(float2*)&red[oct * 4096 + sl * 256 + r * 32 + 2 * bp] = v;
    }
}
__device__ __forceinline__ float fu_sum16(const float* red, int oct, int row, int b) {
    float s = 0.f;
#pragma unroll
    for (int i = 0; i < 16; i++) s += red[oct * 4096 + i * 256 + row * 32 + b];
    return s;
}

// out epilogue for step tt (oh1 parity = par); CW read from L2-resident g_cw.
__device__ __forceinline__ void out_epi(float* red, float b_out_r,
                                        float* __restrict__ out,
                                        int tt, int par, int j, int jl, int b,
                                        int tid, int wid, int lane) {
    __syncthreads();   // red free for reuse
    if (wid < 16) {
#pragma unroll
        for (int rep = 0; rep < 2; rep++) {
            int b2 = wid * 2 + rep;
            float v0 = g_scores[b2][lane], v1 = g_scores[b2][lane + 32];
            float m = fmaxf(v0, v1);
#pragma unroll
            for (int o = 16; o; o >>= 1) m = fmaxf(m, __shfl_xor_sync(0xffffffffu, m, o));
            float e0 = expf(v0 - m), e1 = expf(v1 - m);
            float ssum = e0 + e1;
#pragma unroll
            for (int o = 16; o; o >>= 1) ssum += __shfl_xor_sync(0xffffffffu, ssum, o);
            float inv = 1.f / ssum;
            red[b2 * 65 + lane] = e0 * inv;
            red[b2 * 65 + lane + 32] = e1 * inv;
        }
    }
    __syncthreads();
    if (tid < 256) {
        const float* cw = g_cw + (size_t)j * (B_ * S_) + b * S_;
        const float* wp = red + b * 65;
        float a = g_oh1[par][b][j] + b_out_r;
#pragma unroll
        for (int s4 = 0; s4 < 16; s4++) {
            float4 c = *(const float4*)(cw + s4 * 4);
            a += wp[s4 * 4 + 0] * c.x + wp[s4 * 4 + 1] * c.y +
                 wp[s4 * 4 + 2] * c.z + wp[s4 * 4 + 3] * c.w;
        }
        out[(size_t)tt * B_ * H_ + (size_t)b * H_ + j] = tanhf(a);
    }
    __syncthreads();
}

// scores for parity pg: all 128 blocks, 16 (b,s) dots each
__device__ __forceinline__ void scores_phase(float* red,
                                             const float* __restrict__ contexts,
                                             int pg, int blk, int tid, int wid, int lane) {
    __syncthreads();
    const int bb = blk & 31, sg = blk >> 5;
    const float* gam = &g_gamma[pg][bb][0];
    for (int i = tid; i < H_; i += NT_) red[i] = gam[i];
    __syncthreads();
    if (wid < 16) {
        int s = sg * 16 + wid;
        const float* cp = contexts + ((size_t)bb * S_ + s) * H_;
        float a = 0.f;
#pragma unroll 8
        for (int k = lane; k < H_; k += 32) a = fmaf(cp[k], red[k], a);
#pragma unroll
        for (int o = 16; o; o >>= 1) a += __shfl_xor_sync(0xffffffffu, a, o);
        if (lane == 0) g_scores[bb][s] = a;
    }
    __syncthreads();
}

// ===========================================================================
// Persistent step kernel. grid NBLK x 512. Software-pipelined, 2 bars/step:
//   prologue A(0) |B|
//   for t: alpha(t): B(t) -> A(t+1) -> out_epi(t-2)   |B|
//          beta(t):  FU(t) -> scores(t-1)             |B|
//   tail: out_epi(T-2) |B| scores(T-1) |B| out_epi(T-1)
// beta(t) fully prestages cell1(t+1) (w + x, both published & bar-ordered).
// ===========================================================================
__global__ void __launch_bounds__(NT_, 1) k_steps(const float* __restrict__ Whh0,
                                                  const float* __restrict__ Wih1,
                                                  const float* __restrict__ Whh1,
                                                  const float* __restrict__ bih1,
                                                  const float* __restrict__ bhh1,
                                                  const float* __restrict__ W_in,
                                                  const float* __restrict__ b_in,
                                                  const float* __restrict__ W_out,
                                                  const float* __restrict__ b_out,
                                                  const float* __restrict__ contexts,
                                                  float* __restrict__ out) {
    extern __shared__ float sm[];
    __shared__ unsigned long long mbar[2];
    const int tid = threadIdx.x, wid = tid >> 5, lane = tid & 31;
    const int blk = blockIdx.x;
    const int jl = tid >> 5, b = tid & 31;   // epilogue map (tid<256)
    const int j = blk * 8 + jl;
    float* red = sm + 4 * BUF;

    if (tid == 0) { mb_init(&mbar[0]); mb_init(&mbar[1]); }
    __syncthreads();
    Bufs Bf = {sm, sm + 2 * BUF, sm + BUF, sm + 3 * BUF,
               su32(&mbar[0]), su32(&mbar[1])};
    unsigned ph[2] = {0u, 0u};

    // hoisted per-thread constants
    float bi1[4], b_in_r = 0.f, b_out_r = 0.f;
    if (tid < 256) {
#pragma unroll
        for (int g = 0; g < 4; g++) bi1[g] = bih1[g * H_ + j] + bhh1[g * H_ + j];
        b_in_r = b_in[j];
        b_out_r = b_out[j];
    }

    // ---- prologue: A(0) = cell0(t=0) ----
    {
        Job A0 = {&g_hbuf[1][0][0][0], nullptr, nullptr, Whh0, nullptr, nullptr,
                  (size_t)H_, 0, blk * 8, H_, 32};
        Job B0 = {&g_hbuf[0][0][0][0], &g_hbuf[1][1][0][0], nullptr,
                  Wih1, Whh1, nullptr, (size_t)H_, 0, blk * 8, H_, 32};
        stage_w(Bf, A0, 0, tid); stage_x(Bf, A0, 0, tid);
        stage_w(Bf, A0, 1, tid); stage_x(Bf, A0, 1, tid);
        unsigned long long acc[16] = {};
        run_job<4, 0>(Bf, A0, &B0, false, acc, ph, tid, wid, lane);
        __syncthreads();
        red32_write(red, acc, wid, lane);
        __syncthreads();
        if (tid < 256) {
            float v[4];
#pragma unroll
            for (int g = 0; g < 4; g++)
                v[g] = red32_sum8(red, g * 8 + jl, b) +
                       g_pre0[(size_t)(g * H_ + j) * B_ + b];
            float c1 = sigf(v[1]) * g_c[0][b][j] + sigf(v[0]) * tanhf(v[2]);
            g_c[0][b][j] = c1;
            g_hbuf[0][0][b][j] = sigf(v[3]) * tanhf(c1);
        }
    }
    grid_bar();

    for (int t = 0; t < T_; t++) {
        const int cur = t & 1;
        const bool hasA = (t + 1 < T_);

        Job Bt = {&g_hbuf[cur][0][0][0], &g_hbuf[1 - cur][1][0][0], nullptr,
                  Wih1, Whh1, nullptr, (size_t)H_, 0, blk * 8, H_, 32};
        Job An = {&g_hbuf[cur][0][0][0], nullptr, nullptr, Whh0, nullptr, nullptr,
                  (size_t)H_, 0, blk * 8, H_, 32};
        Job FUt = {&g_hbuf[cur][1][0][0], nullptr, nullptr,
                   W_in, nullptr, W_out + H_, (size_t)H_, (size_t)(2 * H_),
                   blk * 8, 8, 16};
        Job Bn = {&g_hbuf[1 - cur][0][0][0], &g_hbuf[cur][1][0][0], nullptr,
                  Wih1, Whh1, nullptr, (size_t)H_, 0, blk * 8, H_, 32};

        // ============ alpha(t): cell1(t), cell0(t+1), out_epi(t-2) ============
        if (t == 0) {   // t>0: beta(t-1) already prestaged Bt fully (w + x)
            stage_x(Bf, Bt, 0, tid);
            stage_x(Bf, Bt, 1, tid);
        }

        // prefetch pre0[t+1]
        float p[4];
        if (hasA && tid < 256) {
            const float* pre = g_pre0 + (size_t)(t + 1) * G_ * B_;
#pragma unroll
            for (int g = 0; g < 4; g++) p[g] = pre[(size_t)(g * H_ + j) * B_ + b];
        }

        {   // B(t) = cell1(t)
            unsigned long long acc[16] = {};
            if (hasA) run_job<8, 0>(Bf, Bt, &An, true, acc, ph, tid, wid, lane);
            else      run_job<8, 0>(Bf, Bt, &FUt, false, acc, ph, tid, wid, lane);
            __syncthreads();
            red32_write(red, acc, wid, lane);
            __syncthreads();
            if (tid < 256) {
                float v[4];
#pragma unroll
                for (int g = 0; g < 4; g++)
                    v[g] = red32_sum8(red, g * 8 + jl, b) + bi1[g];
                float c1 = sigf(v[1]) * g_c[1][b][j] + sigf(v[0]) * tanhf(v[2]);
                g_c[1][b][j] = c1;
                g_hbuf[cur][1][b][j] = sigf(v[3]) * tanhf(c1);
            }
        }
        if (hasA) {  // A(t+1) = cell0(t+1)
            unsigned long long acc[16] = {};
            run_job<4, 0>(Bf, An, &FUt, false, acc, ph, tid, wid, lane);
            __syncthreads();
            red32_write(red, acc, wid, lane);
            __syncthreads();
            if (tid < 256) {
                float v[4];
#pragma unroll
                for (int g = 0; g < 4; g++)
                    v[g] = red32_sum8(red, g * 8 + jl, b) + p[g];
                float c1 = sigf(v[1]) * g_c[0][b][j] + sigf(v[0]) * tanhf(v[2]);
                g_c[0][b][j] = c1;
                g_hbuf[1 - cur][0][b][j] = sigf(v[3]) * tanhf(c1);
            }
        }
        if (t >= 2) out_epi(red, b_out_r, out, t - 2, cur, j, jl, b, tid, wid, lane);
        grid_bar();

        // ============ beta(t): FU(t) = gamma+oh1, scores(t-1) ============
        stage_x(Bf, FUt, 0, tid);
        stage_x(Bf, FUt, 1, tid);
        {
            unsigned long long acc[16] = {};
            // prestage NEXT step's cell1 fully (w + x): x inputs h0(t+1), h1(t)
            // are published and barrier-ordered at this point.
            if (hasA) run_job<4, 1>(Bf, FUt, &Bn, true, acc, ph, tid, wid, lane);
            else      run_job<4, 1>(Bf, FUt, nullptr, false, acc, ph, tid, wid, lane);
            __syncthreads();
            fu_write(red, acc, wid, lane);
            __syncthreads();
            if (tid < 256) {
                g_gamma[cur][b][j] = fu_sum16(red, 0, jl, b) + b_in_r;
                g_oh1[cur][b][j]   = fu_sum16(red, 1, jl, b);
            }
        }
        if (t >= 1) scores_phase(red, contexts, 1 - cur, blk, tid, wid, lane);
        grid_bar();
    }

    // ---- tail ----
    out_epi(red, b_out_r, out, T_ - 2, (T_ - 2) & 1, j, jl, b, tid, wid, lane);
    grid_bar();
    scores_phase(red, contexts, (T_ - 1) & 1, blk, tid, wid, lane);
    grid_bar();
    out_epi(red, b_out_r, out, T_ - 1, (T_ - 1) & 1, j, jl, b, tid, wid, lane);
}

// ===========================================================================
// pre0: grid (G/32, T) x 512. One 32-row GEMM per block (R15 proven variant).
// ===========================================================================
__global__ void __launch_bounds__(NT_, 1) k_pre0(const int* __restrict__ tokens,
                                                 const float* __restrict__ emb,
                                                 const float* __restrict__ Wih0,
                                                 const float* __restrict__ bih0,
                                                 const float* __restrict__ bhh0) {
    extern __shared__ float sm[];
    __shared__ unsigned long long mbar[2];
    __shared__ int toks[B_];
    const int tid = threadIdx.x, wid = tid >> 5, lane = tid & 31;
    const int t = blockIdx.y;
    const int j0 = blockIdx.x * 32;
    float* red = sm + 4 * BUF;

    if (tid == 0) { mb_init(&mbar[0]); mb_init(&mbar[1]); }
    if (tid < B_) toks[tid] = tokens[t * B_ + tid];
    __syncthreads();
    Bufs Bf = {sm, sm + 2 * BUF, sm + BUF, sm + 3 * BUF,
               su32(&mbar[0]), su32(&mbar[1])};
    unsigned ph[2] = {0u, 0u};

    Job P = {emb, nullptr, toks, Wih0, nullptr, nullptr, (size_t)H_, 0, j0, 8, 32};
    stage_w(Bf, P, 0, tid); stage_x(Bf, P, 0, tid);
    stage_w(Bf, P, 1, tid); stage_x(Bf, P, 1, tid);

    unsigned long long acc[16] = {};
    run_job<4, 0>(Bf, P, nullptr, false, acc, ph, tid, wid, lane);
    __syncthreads();
    red32_write(red, acc, wid, lane);
    __syncthreads();

    const int rl = tid >> 5, b = tid & 31;
#pragma unroll
    for (int i = 0; i < 2; i++) {
        int row = rl + i * 16;
        int jj = j0 + row;
        g_pre0[((size_t)t * G_ + jj) * B_ + b] =
            red32_sum8(red, row, b) + bih0[jj] + bhh0[jj];
    }
}

// ===========================================================================
// CW precompute: CW[j][b][s] = contexts[b,s,:].W_out[j,:H]
// grid (H/32 j-tiles, B*S/32 bs-tiles) x 512, single-round red.
// ===========================================================================
__global__ void __launch_bounds__(NT_, 1) k_cw(const float* __restrict__ contexts,
                                               const float* __restrict__ W_out) {
    extern __shared__ float sm[];
    __shared__ unsigned long long mbar[2];
    const int tid = threadIdx.x, wid = tid >> 5, lane = tid & 31;
    const int j0 = blockIdx.x * 32;
    const int bs0 = blockIdx.y * 32;
    float* red = sm + 4 * BUF;

    if (tid == 0) { mb_init(&mbar[0]); mb_init(&mbar[1]); }
    __syncthreads();
    Bufs Bf = {sm, sm + 2 * BUF, sm + BUF, sm + 3 * BUF,
               su32(&mbar[0]), su32(&mbar[1])};
    unsigned ph[2] = {0u, 0u};

    Job P = {contexts + (size_t)bs0 * H_, nullptr, nullptr,
             W_out, nullptr, nullptr, (size_t)(2 * H_), 0, j0, 8, 32};
    stage_w(Bf, P, 0, tid); stage_x(Bf, P, 0, tid);
    stage_w(Bf, P, 1, tid); stage_x(Bf, P, 1, tid);

    unsigned long long acc[16] = {};
    run_job<4, 0>(Bf, P, nullptr, false, acc, ph, tid, wid, lane);
    __syncthreads();
    red32_write(red, acc, wid, lane);
    __syncthreads();

    const int rl = tid >> 5, b = tid & 31;
#pragma unroll
    for (int i = 0; i < 2; i++) {
        int row = rl + i * 16;
        g_cw[(size_t)(j0 + row) * (B_ * S_) + bs0 + b] = red32_sum8(red, row, b);
    }
}

// ---------------------------------------------------------------------------
extern "C" void kernel_launch(void* const* d_in, const int* in_sizes, int n_in,
                              void* d_out, int out_size) {
    const int*   tokens   = (const int*)d_in[0];
    const float* h0       = (const float*)d_in[1];
    const float* c0       = (const float*)d_in[2];
    const float* contexts = (const float*)d_in[3];
    const float* emb      = (const float*)d_in[4];
    const float* W_ih     = (const float*)d_in[5];
    const float* W_hh     = (const float*)d_in[6];
    const float* b_ih     = (const float*)d_in[7];
    const float* b_hh     = (const float*)d_in[8];
    const float* W_in     = (const float*)d_in[9];
    const float* b_in     = (const float*)d_in[10];
    const float* W_out    = (const float*)d_in[11];
    const float* b_out    = (const float*)d_in[12];
    float* out = (float*)d_out;

    cudaFuncSetAttribute(k_pre0,  cudaFuncAttributeMaxDynamicSharedMemorySize, SMEM_BYTES);
    cudaFuncSetAttribute(k_cw,    cudaFuncAttributeMaxDynamicSharedMemorySize, SMEM_BYTES);
    cudaFuncSetAttribute(k_steps, cudaFuncAttributeMaxDynamicSharedMemorySize, SMEM_BYTES);

    const size_t stateBytes = (size_t)L_ * B_ * H_ * sizeof(float);

    // init state: h -> hbuf[1] (prev of t=0), c -> g_c
    cudaMemcpyToSymbolAsync(g_hbuf, h0, stateBytes, stateBytes,
                            cudaMemcpyDeviceToDevice, 0);
    cudaMemcpyToSymbolAsync(g_c, c0, stateBytes, 0, cudaMemcpyDeviceToDevice, 0);

    // hoisted precomputes
    k_pre0<<<dim3(G_ / 32, T_), NT_, SMEM_BYTES>>>(tokens, emb, W_ih, b_ih, b_hh);
    k_cw<<<dim3(H_ / 32, (B_ * S_) / 32), NT_, SMEM_BYTES>>>(contexts, W_out);

    const float* Wih1 = W_ih + (size_t)G_ * H_;
    const float* Whh1 = W_hh + (size_t)G_ * H_;
    const float* bih1 = b_ih + G_;
    const float* bhh1 = b_hh + G_;

    // entire recurrence in ONE persistent kernel
    k_steps<<<NBLK, NT_, SMEM_BYTES>>>(W_hh, Wih1, Whh1, bih1, bhh1,
                                       W_in, b_in, W_out, b_out, contexts, out);

    // hT (in hbuf[1] since (T-1)&1 == 1), then cT
    cudaMemcpyFromSymbolAsync(out + (size_t)T_ * B_ * H_, g_hbuf, stateBytes,
                              stateBytes, cudaMemcpyDeviceToDevice, 0);
    cudaMemcpyFromSymbolAsync(out + (size_t)T_ * B_ * H_ + (size_t)L_ * B_ * H_,
                              g_c, stateBytes, 0, cudaMemcpyDeviceToDevice, 0);
}